// round 5
// baseline (speedup 1.0000x reference)
#include <cuda_runtime.h>
#include <cstdint>

#define E 1024
#define R 16
#define BATCH 4
#define S 2048
#define BS (BATCH * S)

// ---------------- device scratch ----------------
__device__ float g_Weff[3][(size_t)E * E];                 // 12 MB
__device__ float g_QKV[3][(size_t)BATCH * S * E];          // 96 MB
__device__ float g_Vt[(size_t)BATCH * S * E];              // 32 MB (V^T per batch: [E][S])
__device__ float g_scores[(size_t)BATCH * S * S];          // 64 MB
__device__ float g_attnout[(size_t)BATCH * S * E];         // 32 MB

#define SEL_EXT   0
#define SEL_WEFF  1
#define SEL_QKV   2
#define SEL_SCORE 3
#define SEL_AOUT  4
#define SEL_VT    5

__device__ __forceinline__ float* resolve_buf(int sel, const float* ext) {
    switch (sel) {
        case SEL_WEFF:  return &g_Weff[0][0];
        case SEL_QKV:   return &g_QKV[0][0];
        case SEL_SCORE: return &g_scores[0];
        case SEL_AOUT:  return &g_attnout[0];
        case SEL_VT:    return &g_Vt[0];
        default:        return (float*)ext;
    }
}

// ---------------- tf32 helpers ----------------
__device__ __forceinline__ uint32_t to_tf32(float x) {
    uint32_t r;
    asm("cvt.rna.tf32.f32 %0, %1;" : "=r"(r) : "f"(x));
    return r;
}

__device__ __forceinline__ void mma_tf32(float* c, const uint32_t* a, const uint32_t* b) {
    asm volatile("mma.sync.aligned.m16n8k8.row.col.f32.tf32.tf32.f32 "
        "{%0,%1,%2,%3}, {%4,%5,%6,%7}, {%8,%9}, {%0,%1,%2,%3};"
        : "+f"(c[0]), "+f"(c[1]), "+f"(c[2]), "+f"(c[3])
        : "r"(a[0]), "r"(a[1]), "r"(a[2]), "r"(a[3]), "r"(b[0]), "r"(b[1]));
}

// ---------------- W_eff = W + B @ A ----------------
__global__ __launch_bounds__(256) void weff_kernel(
    const float* __restrict__ Wq, const float* __restrict__ Wk, const float* __restrict__ Wv,
    const float* __restrict__ Aq, const float* __restrict__ Bq,
    const float* __restrict__ Ak, const float* __restrict__ Bk,
    const float* __restrict__ Av, const float* __restrict__ Bv)
{
    const int z = blockIdx.z;
    const float* W  = (z == 0) ? Wq : (z == 1) ? Wk : Wv;
    const float* Am = (z == 0) ? Aq : (z == 1) ? Ak : Av;
    const float* Bm = (z == 0) ? Bq : (z == 1) ? Bk : Bv;
    const int idx = blockIdx.x * 256 + threadIdx.x;
    const int f = idx >> 10;
    const int e = idx & 1023;
    float sum = W[idx];
#pragma unroll
    for (int r = 0; r < R; r++)
        sum += Bm[f * R + r] * Am[r * E + e];
    g_Weff[z][idx] = sum;
}

// ---------------- V transpose: Vt[b][e][s] = V[b][s][e] ----------------
__global__ __launch_bounds__(256) void transpose_v_kernel()
{
    __shared__ float t[32][33];
    const int b = blockIdx.z;
    const int s0 = blockIdx.x * 32;
    const int e0 = blockIdx.y * 32;
    const int tx = threadIdx.x & 31;
    const int ty = threadIdx.x >> 5;   // 0..7
    const float* V = &g_QKV[2][0] + (long long)b * S * E;
    float* Vt = &g_Vt[0] + (long long)b * S * E;
#pragma unroll
    for (int r = 0; r < 4; r++)
        t[ty + r * 8][tx] = V[(long long)(s0 + ty + r * 8) * E + e0 + tx];
    __syncthreads();
#pragma unroll
    for (int r = 0; r < 4; r++)
        Vt[(long long)(e0 + ty + r * 8) * S + s0 + tx] = t[tx][ty + r * 8];
}

// ---------------- split-TF32 HMMA GEMM ----------------
// C[M,N] = alpha * A[M,K] @ B[N,K]^T (row-major), fp32-grade accuracy via
// 3-term split: A,B -> (hi, lo) tf32; acc += Ah*Bh + Al*Bh + Ah*Bl.
// CTA 128x128x32, 16 warps (4x4), warp tile 32x32 of m16n8k8 fragments.
// Smem in MMA FRAGMENT ORDER (conflict-free LDS.128/LDS.64 at compute).
//  A: fb = kc*8 + (m>>4), idx = fb*128 + lane*4 + reg
//  B: fb = kc*16 + (n>>3), idx = fb*64 + lane*2 + reg
// Planes (floats): aHi 0, aLo 4096, bHi 8192, bLo 12288; buffer stride 16384.
#define GEMM_SMEM_BYTES (2 * 16384 * 4)
#define NTHREADS 512

__global__ __launch_bounds__(NTHREADS, 1) void gemm_hmma(
    const float* extA, int selA, long long offA, int ldA, long long sA,
    const float* extB, int selB, long long offB, int ldB, long long sB,
    float* extC, int selC, long long offC, int ldC, long long sC,
    int K, float alpha)
{
    extern __shared__ float smf[];
    const int tid = threadIdx.x;
    const int wid = tid >> 5, lane = tid & 31;
    const int g = lane >> 2, t4 = lane & 3;
    const int warp_m = wid & 3, warp_n = wid >> 2;   // 4x4 warps, 32x32 warp tile

    const float* Ag = resolve_buf(selA, extA) + offA + (long long)blockIdx.z * sA
                      + (long long)blockIdx.y * 128 * ldA;
    const float* Bg = resolve_buf(selB, extB) + offB + (long long)blockIdx.z * sB
                      + (long long)blockIdx.x * 128 * ldB;
    float* Cg = resolve_buf(selC, extC) + offC + (long long)blockIdx.z * sC;

    float acc[2][4][4];
#pragma unroll
    for (int i = 0; i < 2; i++)
#pragma unroll
        for (int j = 0; j < 4; j++)
#pragma unroll
            for (int q = 0; q < 4; q++) acc[i][j][q] = 0.f;

    float4 va[2], vb[2];

    // global fetch of one 128x32 A tile + 128x32 B tile (2 float4 per thread each)
    auto ldg = [&](int step) {
#pragma unroll
        for (int j = 0; j < 2; j++) {
            const int i = tid + j * NTHREADS;        // 0..1023 float4 slots
            const int row = i >> 3, q = i & 7;
            va[j] = *reinterpret_cast<const float4*>(Ag + (long long)row * ldA + step * 32 + q * 4);
            vb[j] = *reinterpret_cast<const float4*>(Bg + (long long)row * ldB + step * 32 + q * 4);
        }
    };

    // convert + scatter-store into fragment-order smem planes
    auto sts = [&](int s) {
        float* base = smf + s * 16384;
#pragma unroll
        for (int j = 0; j < 2; j++) {
            const int i = tid + j * NTHREADS;
            const int m = i >> 3, q = i & 7;
            const int kc = q >> 1, qodd = q & 1;
            // A
            {
                const int fb = kc * 8 + (m >> 4);
                const int regb = ((m >> 3) & 1) + 2 * qodd;
                const int lbase = (m & 7) * 4;
                const float vals[4] = { va[j].x, va[j].y, va[j].z, va[j].w };
#pragma unroll
                for (int jj = 0; jj < 4; jj++) {
                    const int idx = fb * 128 + (lbase + jj) * 4 + regb;
                    const uint32_t h = to_tf32(vals[jj]);
                    base[idx] = __uint_as_float(h);
                    base[4096 + idx] = __uint_as_float(to_tf32(vals[jj] - __uint_as_float(h)));
                }
            }
            // B
            {
                const int fb = kc * 16 + (m >> 3);
                const int lbase = (m & 7) * 4;
                const float vals[4] = { vb[j].x, vb[j].y, vb[j].z, vb[j].w };
#pragma unroll
                for (int jj = 0; jj < 4; jj++) {
                    const int idx = fb * 64 + (lbase + jj) * 2 + qodd;
                    const uint32_t h = to_tf32(vals[jj]);
                    base[8192 + idx] = __uint_as_float(h);
                    base[12288 + idx] = __uint_as_float(to_tf32(vals[jj] - __uint_as_float(h)));
                }
            }
        }
    };

    auto compute = [&](int s) {
        const float* base = smf + s * 16384;
#pragma unroll
        for (int kc = 0; kc < 4; kc++) {
            uint32_t aF[2][2][4], bF[2][4][2];
#pragma unroll
            for (int mt = 0; mt < 2; mt++) {
                const int fb = kc * 8 + warp_m * 2 + mt;
                const uint4 h = *reinterpret_cast<const uint4*>(base + fb * 128 + lane * 4);
                const uint4 l = *reinterpret_cast<const uint4*>(base + 4096 + fb * 128 + lane * 4);
                aF[0][mt][0] = h.x; aF[0][mt][1] = h.y; aF[0][mt][2] = h.z; aF[0][mt][3] = h.w;
                aF[1][mt][0] = l.x; aF[1][mt][1] = l.y; aF[1][mt][2] = l.z; aF[1][mt][3] = l.w;
            }
#pragma unroll
            for (int nt = 0; nt < 4; nt++) {
                const int fb = kc * 16 + warp_n * 4 + nt;
                const uint2 h = *reinterpret_cast<const uint2*>(base + 8192 + fb * 64 + lane * 2);
                const uint2 l = *reinterpret_cast<const uint2*>(base + 12288 + fb * 64 + lane * 2);
                bF[0][nt][0] = h.x; bF[0][nt][1] = h.y;
                bF[1][nt][0] = l.x; bF[1][nt][1] = l.y;
            }
#pragma unroll
            for (int mt = 0; mt < 2; mt++)
#pragma unroll
                for (int nt = 0; nt < 4; nt++)
                    mma_tf32(acc[mt][nt], aF[0][mt], bF[0][nt]);
#pragma unroll
            for (int mt = 0; mt < 2; mt++)
#pragma unroll
                for (int nt = 0; nt < 4; nt++)
                    mma_tf32(acc[mt][nt], aF[1][mt], bF[0][nt]);
#pragma unroll
            for (int mt = 0; mt < 2; mt++)
#pragma unroll
                for (int nt = 0; nt < 4; nt++)
                    mma_tf32(acc[mt][nt], aF[0][mt], bF[1][nt]);
        }
    };

    const int nsteps = K / 32;
    ldg(0);
    sts(0);
    __syncthreads();
    for (int step = 0; step < nsteps; step++) {
        const int s = step & 1;
        if (step + 1 < nsteps) ldg(step + 1);
        compute(s);
        if (step + 1 < nsteps) sts(1 - s);
        __syncthreads();
    }

    // epilogue: warp tile rows warp_m*32 .. +31, cols warp_n*32 .. +31
#pragma unroll
    for (int mt = 0; mt < 2; mt++) {
        const long long row = (long long)blockIdx.y * 128 + warp_m * 32 + mt * 16 + g;
        const long long col0 = (long long)blockIdx.x * 128 + warp_n * 32;
#pragma unroll
        for (int nt = 0; nt < 4; nt++) {
            const long long col = col0 + nt * 8 + t4 * 2;
            float2 v0 = make_float2(acc[mt][nt][0] * alpha, acc[mt][nt][1] * alpha);
            float2 v1 = make_float2(acc[mt][nt][2] * alpha, acc[mt][nt][3] * alpha);
            *reinterpret_cast<float2*>(Cg + row * ldC + col) = v0;
            *reinterpret_cast<float2*>(Cg + (row + 8) * ldC + col) = v1;
        }
    }
}

// ---------------- row softmax over S=2048 ----------------
__global__ __launch_bounds__(256) void softmax_kernel()
{
    const long long row = blockIdx.x;
    float* p = &g_scores[0] + row * (long long)S;
    const int t = threadIdx.x;

    float v[8];
    float m = -1e30f;
#pragma unroll
    for (int i = 0; i < 8; i++) {
        v[i] = p[t + i * 256];
        m = fmaxf(m, v[i]);
    }
    __shared__ float red[8];
#pragma unroll
    for (int o = 16; o; o >>= 1) m = fmaxf(m, __shfl_xor_sync(0xffffffffu, m, o));
    if ((t & 31) == 0) red[t >> 5] = m;
    __syncthreads();
    float mx = red[0];
#pragma unroll
    for (int w = 1; w < 8; w++) mx = fmaxf(mx, red[w]);

    float s = 0.f;
#pragma unroll
    for (int i = 0; i < 8; i++) {
        v[i] = __expf(v[i] - mx);
        s += v[i];
    }
#pragma unroll
    for (int o = 16; o; o >>= 1) s += __shfl_xor_sync(0xffffffffu, s, o);
    __syncthreads();
    if ((t & 31) == 0) red[t >> 5] = s;
    __syncthreads();
    float tot = 0.f;
#pragma unroll
    for (int w = 0; w < 8; w++) tot += red[w];
    const float inv = 1.0f / tot;
#pragma unroll
    for (int i = 0; i < 8; i++) p[t + i * 256] = v[i] * inv;
}

// ---------------- launch ----------------
extern "C" void kernel_launch(void* const* d_in, const int* in_sizes, int n_in,
                              void* d_out, int out_size)
{
    (void)in_sizes; (void)n_in; (void)out_size;
    const float* query = (const float*)d_in[0];
    const float* key   = (const float*)d_in[1];
    const float* value = (const float*)d_in[2];
    const float* Qw    = (const float*)d_in[3];
    const float* Kw    = (const float*)d_in[4];
    const float* Vw    = (const float*)d_in[5];
    const float* Qa    = (const float*)d_in[6];
    const float* Qb    = (const float*)d_in[7];
    const float* Ka    = (const float*)d_in[8];
    const float* Kb    = (const float*)d_in[9];
    const float* Va    = (const float*)d_in[10];
    const float* Vb    = (const float*)d_in[11];
    const float* Ow    = (const float*)d_in[12];
    float* out = (float*)d_out;

    static bool attr_done = false;
    if (!attr_done) {
        cudaFuncSetAttribute(gemm_hmma, cudaFuncAttributeMaxDynamicSharedMemorySize,
                             GEMM_SMEM_BYTES);
        attr_done = true;
    }

    const long long EE  = (long long)E * E;
    const long long BSE = (long long)BATCH * S * E;
    const long long SE  = (long long)S * E;
    const long long SS  = (long long)S * S;

    // 1. fold LoRA into weights
    weff_kernel<<<dim3(E * E / 256, 1, 3), 256>>>(Qw, Kw, Vw, Qa, Qb, Ka, Kb, Va, Vb);

    // 2. Q/K/V projections: [8192,1024] = X @ Weff^T
    const float* xs[3] = { query, key, value };
    for (int p = 0; p < 3; p++) {
        gemm_hmma<<<dim3(E / 128, BS / 128, 1), NTHREADS, GEMM_SMEM_BYTES>>>(
            xs[p],   SEL_EXT,  0,       E, 0,
            nullptr, SEL_WEFF, p * EE,  E, 0,
            nullptr, SEL_QKV,  p * BSE, E, 0,
            E, 1.0f);
    }

    // 3. transpose V -> Vt[b][e][s]
    transpose_v_kernel<<<dim3(S / 32, E / 32, BATCH), 256>>>();

    // 4. scores = Q @ K^T / 32
    gemm_hmma<<<dim3(S / 128, S / 128, BATCH), NTHREADS, GEMM_SMEM_BYTES>>>(
        nullptr, SEL_QKV,   0,   E, SE,
        nullptr, SEL_QKV,   BSE, E, SE,
        nullptr, SEL_SCORE, 0,   S, SS,
        E, 1.0f / 32.0f);

    // 5. softmax rows
    softmax_kernel<<<BATCH * S, 256>>>();

    // 6. attn_out = P @ Vt^T   (NT with Vt as [E,S] K-major)
    gemm_hmma<<<dim3(E / 128, S / 128, BATCH), NTHREADS, GEMM_SMEM_BYTES>>>(
        nullptr, SEL_SCORE, 0, S, SS,
        nullptr, SEL_VT,    0, S, SE,
        nullptr, SEL_AOUT,  0, E, SE,
        S, 1.0f);

    // 7. final = attn_out @ O^T
    gemm_hmma<<<dim3(E / 128, BS / 128, 1), NTHREADS, GEMM_SMEM_BYTES>>>(
        nullptr, SEL_AOUT, 0, E, 0,
        Ow,      SEL_EXT,  0, E, 0,
        out,     SEL_EXT,  0, E, 0,
        E, 1.0f);
}

// round 6
// speedup vs baseline: 2.0552x; 2.0552x over previous
#include <cuda_runtime.h>
#include <cstdint>

#define E 1024
#define R 16
#define BATCH 4
#define S 2048
#define BS (BATCH * S)

// ---------------- device scratch ----------------
__device__ float g_Weff[3][(size_t)E * E];                 // 12 MB
__device__ float g_QKV[3][(size_t)BATCH * S * E];          // 96 MB
__device__ float g_Vt[(size_t)BATCH * S * E];              // 32 MB (V^T per batch: [E][S])
__device__ float g_scores[(size_t)BATCH * S * S];          // 64 MB
__device__ float g_attnout[(size_t)BATCH * S * E];         // 32 MB

#define SEL_EXT   0
#define SEL_WEFF  1
#define SEL_QKV   2
#define SEL_SCORE 3
#define SEL_AOUT  4
#define SEL_VT    5

__device__ __forceinline__ float* resolve_buf(int sel, const float* ext) {
    switch (sel) {
        case SEL_WEFF:  return &g_Weff[0][0];
        case SEL_QKV:   return &g_QKV[0][0];
        case SEL_SCORE: return &g_scores[0];
        case SEL_AOUT:  return &g_attnout[0];
        case SEL_VT:    return &g_Vt[0];
        default:        return (float*)ext;
    }
}

// ---------------- bf16 helpers ----------------
// pack two floats to bf16x2: low half = x0, high half = x1
__device__ __forceinline__ uint32_t bf16x2_rn(float x0, float x1) {
    uint32_t r;
    asm("cvt.rn.bf16x2.f32 %0, %1, %2;" : "=r"(r) : "f"(x1), "f"(x0));
    return r;
}
__device__ __forceinline__ float bf_lo_f(uint32_t w) { return __uint_as_float(w << 16); }
__device__ __forceinline__ float bf_hi_f(uint32_t w) { return __uint_as_float(w & 0xffff0000u); }

__device__ __forceinline__ void mma_bf16(float* c, const uint32_t* a, const uint32_t* b) {
    asm volatile("mma.sync.aligned.m16n8k16.row.col.f32.bf16.bf16.f32 "
        "{%0,%1,%2,%3}, {%4,%5,%6,%7}, {%8,%9}, {%0,%1,%2,%3};"
        : "+f"(c[0]), "+f"(c[1]), "+f"(c[2]), "+f"(c[3])
        : "r"(a[0]), "r"(a[1]), "r"(a[2]), "r"(a[3]), "r"(b[0]), "r"(b[1]));
}

// ---------------- W_eff = W + B @ A ----------------
__global__ __launch_bounds__(256) void weff_kernel(
    const float* __restrict__ Wq, const float* __restrict__ Wk, const float* __restrict__ Wv,
    const float* __restrict__ Aq, const float* __restrict__ Bq,
    const float* __restrict__ Ak, const float* __restrict__ Bk,
    const float* __restrict__ Av, const float* __restrict__ Bv)
{
    const int z = blockIdx.z;
    const float* W  = (z == 0) ? Wq : (z == 1) ? Wk : Wv;
    const float* Am = (z == 0) ? Aq : (z == 1) ? Ak : Av;
    const float* Bm = (z == 0) ? Bq : (z == 1) ? Bk : Bv;
    const int idx = blockIdx.x * 256 + threadIdx.x;
    const int f = idx >> 10;
    const int e = idx & 1023;
    float sum = W[idx];
#pragma unroll
    for (int r = 0; r < R; r++)
        sum += Bm[f * R + r] * Am[r * E + e];
    g_Weff[z][idx] = sum;
}

// ---------------- V transpose: Vt[b][e][s] = V[b][s][e] ----------------
__global__ __launch_bounds__(256) void transpose_v_kernel()
{
    __shared__ float t[32][33];
    const int b = blockIdx.z;
    const int s0 = blockIdx.x * 32;
    const int e0 = blockIdx.y * 32;
    const int tx = threadIdx.x & 31;
    const int ty = threadIdx.x >> 5;   // 0..7
    const float* V = &g_QKV[2][0] + (long long)b * S * E;
    float* Vt = &g_Vt[0] + (long long)b * S * E;
#pragma unroll
    for (int r = 0; r < 4; r++)
        t[ty + r * 8][tx] = V[(long long)(s0 + ty + r * 8) * E + e0 + tx];
    __syncthreads();
#pragma unroll
    for (int r = 0; r < 4; r++)
        Vt[(long long)(e0 + ty + r * 8) * S + s0 + tx] = t[tx][ty + r * 8];
}

// ---------------- split-BF16 4-term HMMA GEMM ----------------
// C[M,N] = alpha * A[M,K] @ B[N,K]^T (row-major). Each fp32 input x -> bf16
// hi = rn(x), lo = rn(x - hi). acc += Ah*Bh + Al*Bh + Ah*Bl + Al*Bl  (exact
// to ~2^-18 per element; fp32 TC accumulate).
// CTA 128x128x32, 8 warps (2x4), warp tile 64x32 of m16n8k16 fragments.
// Smem in MMA FRAGMENT ORDER; each 32-bit word = bf16x2 of (k, k+1).
//  A word: fb = (m>>4)*2 + kc; idx = fb*128 + ((m&7)*4 + tpair)*4 + ((m>>3)&1) + 2*khalf
//  B word: fb = (n>>3)*2 + kc; idx = fb*64  + ((n&7)*4 + tpair)*2 + khalf
// Word planes: aHi 0, aLo 2048, bHi 4096, bLo 6144; buffer stride 8192 words.
#define GEMM_SMEM_BYTES (2 * 8192 * 4)
#define NTHREADS 256

__global__ __launch_bounds__(NTHREADS, 1) void gemm_hmma(
    const float* extA, int selA, long long offA, int ldA, long long sA,
    const float* extB, int selB, long long offB, int ldB, long long sB,
    float* extC, int selC, long long offC, int ldC, long long sC,
    int K, float alpha)
{
    extern __shared__ uint32_t smw[];
    const int tid = threadIdx.x;
    const int wid = tid >> 5, lane = tid & 31;
    const int g = lane >> 2, t4 = lane & 3;
    const int warp_m = wid & 1, warp_n = wid >> 1;   // 2x4 warps, 64x32 warp tile

    const float* Ag = resolve_buf(selA, extA) + offA + (long long)blockIdx.z * sA
                      + (long long)blockIdx.y * 128 * ldA;
    const float* Bg = resolve_buf(selB, extB) + offB + (long long)blockIdx.z * sB
                      + (long long)blockIdx.x * 128 * ldB;
    float* Cg = resolve_buf(selC, extC) + offC + (long long)blockIdx.z * sC;

    float acc[4][4][4];
#pragma unroll
    for (int i = 0; i < 4; i++)
#pragma unroll
        for (int j = 0; j < 4; j++)
#pragma unroll
            for (int q = 0; q < 4; q++) acc[i][j][q] = 0.f;

    float4 va[4], vb[4];

    // fetch one 128x32 A tile + 128x32 B tile (4 float4 per thread each)
    auto ldg = [&](int step) {
#pragma unroll
        for (int j = 0; j < 4; j++) {
            const int i = tid + j * NTHREADS;        // 0..1023 float4 slots
            const int row = i >> 3, q = i & 7;
            va[j] = *reinterpret_cast<const float4*>(Ag + (long long)row * ldA + step * 32 + q * 4);
            vb[j] = *reinterpret_cast<const float4*>(Bg + (long long)row * ldB + step * 32 + q * 4);
        }
    };

    // split + pack bf16x2 + scatter-store into fragment-order planes
    auto sts = [&](int s) {
        uint32_t* base = smw + s * 8192;
#pragma unroll
        for (int j = 0; j < 4; j++) {
            const int i = tid + j * NTHREADS;
            const int m = i >> 3, q = i & 7;
            const int kc = q >> 2;                 // k16 chunk within step
            const int khalf = (q >> 1) & 1;        // k8 half within chunk
            const int tp = (q & 1) * 2;            // fragment k-pair base
            // two bf16x2 words per float4: pairs (x,y) and (z,w)
            const float xs[4] = { va[j].x, va[j].y, va[j].z, va[j].w };
            const float ys[4] = { vb[j].x, vb[j].y, vb[j].z, vb[j].w };
            // A
            {
                const int fb = (m >> 4) * 2 + kc;
                const int reg = ((m >> 3) & 1) + 2 * khalf;
#pragma unroll
                for (int w = 0; w < 2; w++) {
                    const float x0 = xs[w * 2], x1 = xs[w * 2 + 1];
                    const uint32_t h = bf16x2_rn(x0, x1);
                    const uint32_t l = bf16x2_rn(x0 - bf_lo_f(h), x1 - bf_hi_f(h));
                    const int idx = fb * 128 + ((m & 7) * 4 + tp + w) * 4 + reg;
                    base[idx] = h;
                    base[2048 + idx] = l;
                }
            }
            // B (row n = m)
            {
                const int fb = (m >> 3) * 2 + kc;
#pragma unroll
                for (int w = 0; w < 2; w++) {
                    const float x0 = ys[w * 2], x1 = ys[w * 2 + 1];
                    const uint32_t h = bf16x2_rn(x0, x1);
                    const uint32_t l = bf16x2_rn(x0 - bf_lo_f(h), x1 - bf_hi_f(h));
                    const int idx = fb * 64 + ((m & 7) * 4 + tp + w) * 2 + khalf;
                    base[4096 + idx] = h;
                    base[6144 + idx] = l;
                }
            }
        }
    };

    auto compute = [&](int s) {
        const uint32_t* base = smw + s * 8192;
#pragma unroll
        for (int kc = 0; kc < 2; kc++) {
            uint32_t aF[2][4][4], bF[2][4][2];
#pragma unroll
            for (int mt = 0; mt < 4; mt++) {
                const int fb = (warp_m * 4 + mt) * 2 + kc;
                const uint4 h = *reinterpret_cast<const uint4*>(base + fb * 128 + lane * 4);
                const uint4 l = *reinterpret_cast<const uint4*>(base + 2048 + fb * 128 + lane * 4);
                aF[0][mt][0] = h.x; aF[0][mt][1] = h.y; aF[0][mt][2] = h.z; aF[0][mt][3] = h.w;
                aF[1][mt][0] = l.x; aF[1][mt][1] = l.y; aF[1][mt][2] = l.z; aF[1][mt][3] = l.w;
            }
#pragma unroll
            for (int nt = 0; nt < 4; nt++) {
                const int fb = (warp_n * 4 + nt) * 2 + kc;
                const uint2 h = *reinterpret_cast<const uint2*>(base + 4096 + fb * 64 + lane * 2);
                const uint2 l = *reinterpret_cast<const uint2*>(base + 6144 + fb * 64 + lane * 2);
                bF[0][nt][0] = h.x; bF[0][nt][1] = h.y;
                bF[1][nt][0] = l.x; bF[1][nt][1] = l.y;
            }
#pragma unroll
            for (int mt = 0; mt < 4; mt++)
#pragma unroll
                for (int nt = 0; nt < 4; nt++)
                    mma_bf16(acc[mt][nt], aF[0][mt], bF[0][nt]);
#pragma unroll
            for (int mt = 0; mt < 4; mt++)
#pragma unroll
                for (int nt = 0; nt < 4; nt++)
                    mma_bf16(acc[mt][nt], aF[1][mt], bF[0][nt]);
#pragma unroll
            for (int mt = 0; mt < 4; mt++)
#pragma unroll
                for (int nt = 0; nt < 4; nt++)
                    mma_bf16(acc[mt][nt], aF[0][mt], bF[1][nt]);
#pragma unroll
            for (int mt = 0; mt < 4; mt++)
#pragma unroll
                for (int nt = 0; nt < 4; nt++)
                    mma_bf16(acc[mt][nt], aF[1][mt], bF[1][nt]);
        }
    };

    const int nsteps = K / 32;
    ldg(0);
    sts(0);
    __syncthreads();
    for (int step = 0; step < nsteps; step++) {
        const int s = step & 1;
        if (step + 1 < nsteps) ldg(step + 1);
        compute(s);
        if (step + 1 < nsteps) sts(1 - s);
        __syncthreads();
    }

    // epilogue: warp rows warp_m*64 .. +63, cols warp_n*32 .. +31
#pragma unroll
    for (int mt = 0; mt < 4; mt++) {
        const long long row = (long long)blockIdx.y * 128 + warp_m * 64 + mt * 16 + g;
        const long long col0 = (long long)blockIdx.x * 128 + warp_n * 32;
#pragma unroll
        for (int nt = 0; nt < 4; nt++) {
            const long long col = col0 + nt * 8 + t4 * 2;
            float2 v0 = make_float2(acc[mt][nt][0] * alpha, acc[mt][nt][1] * alpha);
            float2 v1 = make_float2(acc[mt][nt][2] * alpha, acc[mt][nt][3] * alpha);
            *reinterpret_cast<float2*>(Cg + row * ldC + col) = v0;
            *reinterpret_cast<float2*>(Cg + (row + 8) * ldC + col) = v1;
        }
    }
}

// ---------------- row softmax over S=2048 ----------------
__global__ __launch_bounds__(256) void softmax_kernel()
{
    const long long row = blockIdx.x;
    float* p = &g_scores[0] + row * (long long)S;
    const int t = threadIdx.x;

    float v[8];
    float m = -1e30f;
#pragma unroll
    for (int i = 0; i < 8; i++) {
        v[i] = p[t + i * 256];
        m = fmaxf(m, v[i]);
    }
    __shared__ float red[8];
#pragma unroll
    for (int o = 16; o; o >>= 1) m = fmaxf(m, __shfl_xor_sync(0xffffffffu, m, o));
    if ((t & 31) == 0) red[t >> 5] = m;
    __syncthreads();
    float mx = red[0];
#pragma unroll
    for (int w = 1; w < 8; w++) mx = fmaxf(mx, red[w]);

    float s = 0.f;
#pragma unroll
    for (int i = 0; i < 8; i++) {
        v[i] = __expf(v[i] - mx);
        s += v[i];
    }
#pragma unroll
    for (int o = 16; o; o >>= 1) s += __shfl_xor_sync(0xffffffffu, s, o);
    __syncthreads();
    if ((t & 31) == 0) red[t >> 5] = s;
    __syncthreads();
    float tot = 0.f;
#pragma unroll
    for (int w = 0; w < 8; w++) tot += red[w];
    const float inv = 1.0f / tot;
#pragma unroll
    for (int i = 0; i < 8; i++) p[t + i * 256] = v[i] * inv;
}

// ---------------- launch ----------------
extern "C" void kernel_launch(void* const* d_in, const int* in_sizes, int n_in,
                              void* d_out, int out_size)
{
    (void)in_sizes; (void)n_in; (void)out_size;
    const float* query = (const float*)d_in[0];
    const float* key   = (const float*)d_in[1];
    const float* value = (const float*)d_in[2];
    const float* Qw    = (const float*)d_in[3];
    const float* Kw    = (const float*)d_in[4];
    const float* Vw    = (const float*)d_in[5];
    const float* Qa    = (const float*)d_in[6];
    const float* Qb    = (const float*)d_in[7];
    const float* Ka    = (const float*)d_in[8];
    const float* Kb    = (const float*)d_in[9];
    const float* Va    = (const float*)d_in[10];
    const float* Vb    = (const float*)d_in[11];
    const float* Ow    = (const float*)d_in[12];
    float* out = (float*)d_out;

    static bool attr_done = false;
    if (!attr_done) {
        cudaFuncSetAttribute(gemm_hmma, cudaFuncAttributeMaxDynamicSharedMemorySize,
                             GEMM_SMEM_BYTES);
        attr_done = true;
    }

    const long long EE  = (long long)E * E;
    const long long BSE = (long long)BATCH * S * E;
    const long long SE  = (long long)S * E;
    const long long SS  = (long long)S * S;

    // 1. fold LoRA into weights
    weff_kernel<<<dim3(E * E / 256, 1, 3), 256>>>(Qw, Kw, Vw, Qa, Qb, Ka, Kb, Va, Vb);

    // 2. Q/K/V projections: [8192,1024] = X @ Weff^T
    const float* xs[3] = { query, key, value };
    for (int p = 0; p < 3; p++) {
        gemm_hmma<<<dim3(E / 128, BS / 128, 1), NTHREADS, GEMM_SMEM_BYTES>>>(
            xs[p],   SEL_EXT,  0,       E, 0,
            nullptr, SEL_WEFF, p * EE,  E, 0,
            nullptr, SEL_QKV,  p * BSE, E, 0,
            E, 1.0f);
    }

    // 3. transpose V -> Vt[b][e][s]
    transpose_v_kernel<<<dim3(S / 32, E / 32, BATCH), 256>>>();

    // 4. scores = Q @ K^T / 32
    gemm_hmma<<<dim3(S / 128, S / 128, BATCH), NTHREADS, GEMM_SMEM_BYTES>>>(
        nullptr, SEL_QKV,   0,   E, SE,
        nullptr, SEL_QKV,   BSE, E, SE,
        nullptr, SEL_SCORE, 0,   S, SS,
        E, 1.0f / 32.0f);

    // 5. softmax rows
    softmax_kernel<<<BATCH * S, 256>>>();

    // 6. attn_out = P @ Vt^T   (NT with Vt as [E,S] K-major)
    gemm_hmma<<<dim3(E / 128, S / 128, BATCH), NTHREADS, GEMM_SMEM_BYTES>>>(
        nullptr, SEL_SCORE, 0, S, SS,
        nullptr, SEL_VT,    0, S, SE,
        nullptr, SEL_AOUT,  0, E, SE,
        S, 1.0f);

    // 7. final = attn_out @ O^T
    gemm_hmma<<<dim3(E / 128, BS / 128, 1), NTHREADS, GEMM_SMEM_BYTES>>>(
        nullptr, SEL_AOUT, 0, E, 0,
        Ow,      SEL_EXT,  0, E, 0,
        out,     SEL_EXT,  0, E, 0,
        E, 1.0f);
}

// round 7
// speedup vs baseline: 2.4407x; 1.1876x over previous
#include <cuda_runtime.h>
#include <cstdint>

#define E 1024
#define R 16
#define BATCH 4
#define S 2048
#define BS (BATCH * S)

// ---------------- device scratch ----------------
__device__ float g_Weff[3][(size_t)E * E];                 // 12 MB
__device__ float g_QKV[3][(size_t)BATCH * S * E];          // 96 MB
__device__ float g_Vt[(size_t)BATCH * S * E];              // 32 MB (V^T per batch: [E][S])
__device__ float g_scores[(size_t)BATCH * S * S];          // 64 MB
__device__ float g_attnout[(size_t)BATCH * S * E];         // 32 MB

#define SEL_EXT   0
#define SEL_WEFF  1
#define SEL_QKV   2
#define SEL_SCORE 3
#define SEL_AOUT  4
#define SEL_VT    5

__device__ __forceinline__ float* resolve_buf(int sel, const float* ext) {
    switch (sel) {
        case SEL_WEFF:  return &g_Weff[0][0];
        case SEL_QKV:   return &g_QKV[0][0];
        case SEL_SCORE: return &g_scores[0];
        case SEL_AOUT:  return &g_attnout[0];
        case SEL_VT:    return &g_Vt[0];
        default:        return (float*)ext;
    }
}

// ---------------- bf16 helpers ----------------
// pack two floats to bf16x2: low half = x0, high half = x1
__device__ __forceinline__ uint32_t bf16x2_rn(float x0, float x1) {
    uint32_t r;
    asm("cvt.rn.bf16x2.f32 %0, %1, %2;" : "=r"(r) : "f"(x1), "f"(x0));
    return r;
}
__device__ __forceinline__ float bf_lo_f(uint32_t w) { return __uint_as_float(w << 16); }
__device__ __forceinline__ float bf_hi_f(uint32_t w) { return __uint_as_float(w & 0xffff0000u); }

__device__ __forceinline__ void mma_bf16(float* c, const uint32_t* a, const uint32_t* b) {
    asm volatile("mma.sync.aligned.m16n8k16.row.col.f32.bf16.bf16.f32 "
        "{%0,%1,%2,%3}, {%4,%5,%6,%7}, {%8,%9}, {%0,%1,%2,%3};"
        : "+f"(c[0]), "+f"(c[1]), "+f"(c[2]), "+f"(c[3])
        : "r"(a[0]), "r"(a[1]), "r"(a[2]), "r"(a[3]), "r"(b[0]), "r"(b[1]));
}

// ---------------- W_eff = W + B @ A ----------------
__global__ __launch_bounds__(256) void weff_kernel(
    const float* __restrict__ Wq, const float* __restrict__ Wk, const float* __restrict__ Wv,
    const float* __restrict__ Aq, const float* __restrict__ Bq,
    const float* __restrict__ Ak, const float* __restrict__ Bk,
    const float* __restrict__ Av, const float* __restrict__ Bv)
{
    const int z = blockIdx.z;
    const float* W  = (z == 0) ? Wq : (z == 1) ? Wk : Wv;
    const float* Am = (z == 0) ? Aq : (z == 1) ? Ak : Av;
    const float* Bm = (z == 0) ? Bq : (z == 1) ? Bk : Bv;
    const int idx = blockIdx.x * 256 + threadIdx.x;
    const int f = idx >> 10;
    const int e = idx & 1023;
    float sum = W[idx];
#pragma unroll
    for (int r = 0; r < R; r++)
        sum += Bm[f * R + r] * Am[r * E + e];
    g_Weff[z][idx] = sum;
}

// ---------------- V transpose: Vt[b][e][s] = V[b][s][e] ----------------
__global__ __launch_bounds__(256) void transpose_v_kernel()
{
    __shared__ float t[32][33];
    const int b = blockIdx.z;
    const int s0 = blockIdx.x * 32;
    const int e0 = blockIdx.y * 32;
    const int tx = threadIdx.x & 31;
    const int ty = threadIdx.x >> 5;   // 0..7
    const float* V = &g_QKV[2][0] + (long long)b * S * E;
    float* Vt = &g_Vt[0] + (long long)b * S * E;
#pragma unroll
    for (int r = 0; r < 4; r++)
        t[ty + r * 8][tx] = V[(long long)(s0 + ty + r * 8) * E + e0 + tx];
    __syncthreads();
#pragma unroll
    for (int r = 0; r < 4; r++)
        Vt[(long long)(e0 + ty + r * 8) * S + s0 + tx] = t[tx][ty + r * 8];
}

// ---------------- split-BF16 3-term HMMA GEMM ----------------
// C[M,N] = alpha * A[M,K] @ B[N,K]^T (row-major). Each fp32 input x -> bf16
// hi = rn(x), lo = rn(x - hi). acc += Ah*Bh + Al*Bh + Ah*Bl  (dropped Al*Bl
// term ~2^-16 relative; fp32 TC accumulate).
// CTA 128x128x32, 8 warps (2x4), warp tile 64x32 of m16n8k16 fragments.
// Smem in MMA FRAGMENT ORDER; each 32-bit word = bf16x2 of (k, k+1).
//  A word: fb = (m>>4)*2 + kc; idx = fb*128 + ((m&7)*4 + tpair)*4 + ((m>>3)&1) + 2*khalf
//  B word: fb = (n>>3)*2 + kc; idx = fb*64  + ((n&7)*4 + tpair)*2 + khalf
// Word planes: aHi 0, aLo 2048, bHi 4096, bLo 6144; buffer stride 8192 words.
#define GEMM_SMEM_BYTES (2 * 8192 * 4)
#define NTHREADS 256

__global__ __launch_bounds__(NTHREADS, 1) void gemm_hmma(
    const float* extA, int selA, long long offA, int ldA, long long sA,
    const float* extB, int selB, long long offB, int ldB, long long sB,
    float* extC, int selC, long long offC, int ldC, long long sC,
    int K, float alpha)
{
    extern __shared__ uint32_t smw[];
    const int tid = threadIdx.x;
    const int wid = tid >> 5, lane = tid & 31;
    const int g = lane >> 2, t4 = lane & 3;
    const int warp_m = wid & 1, warp_n = wid >> 1;   // 2x4 warps, 64x32 warp tile

    const float* Ag = resolve_buf(selA, extA) + offA + (long long)blockIdx.z * sA
                      + (long long)blockIdx.y * 128 * ldA;
    const float* Bg = resolve_buf(selB, extB) + offB + (long long)blockIdx.z * sB
                      + (long long)blockIdx.x * 128 * ldB;
    float* Cg = resolve_buf(selC, extC) + offC + (long long)blockIdx.z * sC;

    float acc[4][4][4];
#pragma unroll
    for (int i = 0; i < 4; i++)
#pragma unroll
        for (int j = 0; j < 4; j++)
#pragma unroll
            for (int q = 0; q < 4; q++) acc[i][j][q] = 0.f;

    float4 va[4], vb[4];

    // fetch one 128x32 A tile + 128x32 B tile (4 float4 per thread each)
    auto ldg = [&](int step) {
#pragma unroll
        for (int j = 0; j < 4; j++) {
            const int i = tid + j * NTHREADS;        // 0..1023 float4 slots
            const int row = i >> 3, q = i & 7;
            va[j] = *reinterpret_cast<const float4*>(Ag + (long long)row * ldA + step * 32 + q * 4);
            vb[j] = *reinterpret_cast<const float4*>(Bg + (long long)row * ldB + step * 32 + q * 4);
        }
    };

    // split + pack bf16x2 + scatter-store into fragment-order planes
    auto sts = [&](int s) {
        uint32_t* base = smw + s * 8192;
#pragma unroll
        for (int j = 0; j < 4; j++) {
            const int i = tid + j * NTHREADS;
            const int m = i >> 3, q = i & 7;
            const int kc = q >> 2;                 // k16 chunk within step
            const int khalf = (q >> 1) & 1;        // k8 half within chunk
            const int tp = (q & 1) * 2;            // fragment k-pair base
            const float xs[4] = { va[j].x, va[j].y, va[j].z, va[j].w };
            const float ys[4] = { vb[j].x, vb[j].y, vb[j].z, vb[j].w };
            // A
            {
                const int fb = (m >> 4) * 2 + kc;
                const int reg = ((m >> 3) & 1) + 2 * khalf;
#pragma unroll
                for (int w = 0; w < 2; w++) {
                    const float x0 = xs[w * 2], x1 = xs[w * 2 + 1];
                    const uint32_t h = bf16x2_rn(x0, x1);
                    const uint32_t l = bf16x2_rn(x0 - bf_lo_f(h), x1 - bf_hi_f(h));
                    const int idx = fb * 128 + ((m & 7) * 4 + tp + w) * 4 + reg;
                    base[idx] = h;
                    base[2048 + idx] = l;
                }
            }
            // B (row n = m)
            {
                const int fb = (m >> 3) * 2 + kc;
#pragma unroll
                for (int w = 0; w < 2; w++) {
                    const float x0 = ys[w * 2], x1 = ys[w * 2 + 1];
                    const uint32_t h = bf16x2_rn(x0, x1);
                    const uint32_t l = bf16x2_rn(x0 - bf_lo_f(h), x1 - bf_hi_f(h));
                    const int idx = fb * 64 + ((m & 7) * 4 + tp + w) * 2 + khalf;
                    base[4096 + idx] = h;
                    base[6144 + idx] = l;
                }
            }
        }
    };

    auto compute = [&](int s) {
        const uint32_t* base = smw + s * 8192;
#pragma unroll
        for (int kc = 0; kc < 2; kc++) {
            uint32_t aF[2][4][4], bF[2][4][2];
#pragma unroll
            for (int mt = 0; mt < 4; mt++) {
                const int fb = (warp_m * 4 + mt) * 2 + kc;
                const uint4 h = *reinterpret_cast<const uint4*>(base + fb * 128 + lane * 4);
                const uint4 l = *reinterpret_cast<const uint4*>(base + 2048 + fb * 128 + lane * 4);
                aF[0][mt][0] = h.x; aF[0][mt][1] = h.y; aF[0][mt][2] = h.z; aF[0][mt][3] = h.w;
                aF[1][mt][0] = l.x; aF[1][mt][1] = l.y; aF[1][mt][2] = l.z; aF[1][mt][3] = l.w;
            }
#pragma unroll
            for (int nt = 0; nt < 4; nt++) {
                const int fb = (warp_n * 4 + nt) * 2 + kc;
                const uint2 h = *reinterpret_cast<const uint2*>(base + 4096 + fb * 64 + lane * 2);
                const uint2 l = *reinterpret_cast<const uint2*>(base + 6144 + fb * 64 + lane * 2);
                bF[0][nt][0] = h.x; bF[0][nt][1] = h.y;
                bF[1][nt][0] = l.x; bF[1][nt][1] = l.y;
            }
            // term 1: Ah * Bh
#pragma unroll
            for (int mt = 0; mt < 4; mt++)
#pragma unroll
                for (int nt = 0; nt < 4; nt++)
                    mma_bf16(acc[mt][nt], aF[0][mt], bF[0][nt]);
            // term 2: Al * Bh
#pragma unroll
            for (int mt = 0; mt < 4; mt++)
#pragma unroll
                for (int nt = 0; nt < 4; nt++)
                    mma_bf16(acc[mt][nt], aF[1][mt], bF[0][nt]);
            // term 3: Ah * Bl   (Al*Bl dropped: ~2^-16 relative)
#pragma unroll
            for (int mt = 0; mt < 4; mt++)
#pragma unroll
                for (int nt = 0; nt < 4; nt++)
                    mma_bf16(acc[mt][nt], aF[0][mt], bF[1][nt]);
        }
    };

    const int nsteps = K / 32;
    ldg(0);
    sts(0);
    __syncthreads();
    for (int step = 0; step < nsteps; step++) {
        const int s = step & 1;
        if (step + 1 < nsteps) ldg(step + 1);
        compute(s);
        if (step + 1 < nsteps) sts(1 - s);
        __syncthreads();
    }

    // epilogue: warp rows warp_m*64 .. +63, cols warp_n*32 .. +31
#pragma unroll
    for (int mt = 0; mt < 4; mt++) {
        const long long row = (long long)blockIdx.y * 128 + warp_m * 64 + mt * 16 + g;
        const long long col0 = (long long)blockIdx.x * 128 + warp_n * 32;
#pragma unroll
        for (int nt = 0; nt < 4; nt++) {
            const long long col = col0 + nt * 8 + t4 * 2;
            float2 v0 = make_float2(acc[mt][nt][0] * alpha, acc[mt][nt][1] * alpha);
            float2 v1 = make_float2(acc[mt][nt][2] * alpha, acc[mt][nt][3] * alpha);
            *reinterpret_cast<float2*>(Cg + row * ldC + col) = v0;
            *reinterpret_cast<float2*>(Cg + (row + 8) * ldC + col) = v1;
        }
    }
}

// ---------------- row softmax over S=2048 ----------------
__global__ __launch_bounds__(256) void softmax_kernel()
{
    const long long row = blockIdx.x;
    float* p = &g_scores[0] + row * (long long)S;
    const int t = threadIdx.x;

    float v[8];
    float m = -1e30f;
#pragma unroll
    for (int i = 0; i < 8; i++) {
        v[i] = p[t + i * 256];
        m = fmaxf(m, v[i]);
    }
    __shared__ float red[8];
#pragma unroll
    for (int o = 16; o; o >>= 1) m = fmaxf(m, __shfl_xor_sync(0xffffffffu, m, o));
    if ((t & 31) == 0) red[t >> 5] = m;
    __syncthreads();
    float mx = red[0];
#pragma unroll
    for (int w = 1; w < 8; w++) mx = fmaxf(mx, red[w]);

    float s = 0.f;
#pragma unroll
    for (int i = 0; i < 8; i++) {
        v[i] = __expf(v[i] - mx);
        s += v[i];
    }
#pragma unroll
    for (int o = 16; o; o >>= 1) s += __shfl_xor_sync(0xffffffffu, s, o);
    __syncthreads();
    if ((t & 31) == 0) red[t >> 5] = s;
    __syncthreads();
    float tot = 0.f;
#pragma unroll
    for (int w = 0; w < 8; w++) tot += red[w];
    const float inv = 1.0f / tot;
#pragma unroll
    for (int i = 0; i < 8; i++) p[t + i * 256] = v[i] * inv;
}

// ---------------- launch ----------------
extern "C" void kernel_launch(void* const* d_in, const int* in_sizes, int n_in,
                              void* d_out, int out_size)
{
    (void)in_sizes; (void)n_in; (void)out_size;
    const float* query = (const float*)d_in[0];
    const float* key   = (const float*)d_in[1];
    const float* value = (const float*)d_in[2];
    const float* Qw    = (const float*)d_in[3];
    const float* Kw    = (const float*)d_in[4];
    const float* Vw    = (const float*)d_in[5];
    const float* Qa    = (const float*)d_in[6];
    const float* Qb    = (const float*)d_in[7];
    const float* Ka    = (const float*)d_in[8];
    const float* Kb    = (const float*)d_in[9];
    const float* Va    = (const float*)d_in[10];
    const float* Vb    = (const float*)d_in[11];
    const float* Ow    = (const float*)d_in[12];
    float* out = (float*)d_out;

    static bool attr_done = false;
    if (!attr_done) {
        cudaFuncSetAttribute(gemm_hmma, cudaFuncAttributeMaxDynamicSharedMemorySize,
                             GEMM_SMEM_BYTES);
        attr_done = true;
    }

    const long long EE  = (long long)E * E;
    const long long BSE = (long long)BATCH * S * E;
    const long long SE  = (long long)S * E;
    const long long SS  = (long long)S * S;

    // 1. fold LoRA into weights
    weff_kernel<<<dim3(E * E / 256, 1, 3), 256>>>(Qw, Kw, Vw, Qa, Qb, Ka, Kb, Va, Vb);

    // 2. Q/K/V projections: [8192,1024] = X @ Weff^T
    const float* xs[3] = { query, key, value };
    for (int p = 0; p < 3; p++) {
        gemm_hmma<<<dim3(E / 128, BS / 128, 1), NTHREADS, GEMM_SMEM_BYTES>>>(
            xs[p],   SEL_EXT,  0,       E, 0,
            nullptr, SEL_WEFF, p * EE,  E, 0,
            nullptr, SEL_QKV,  p * BSE, E, 0,
            E, 1.0f);
    }

    // 3. transpose V -> Vt[b][e][s]
    transpose_v_kernel<<<dim3(S / 32, E / 32, BATCH), 256>>>();

    // 4. scores = Q @ K^T / 32
    gemm_hmma<<<dim3(S / 128, S / 128, BATCH), NTHREADS, GEMM_SMEM_BYTES>>>(
        nullptr, SEL_QKV,   0,   E, SE,
        nullptr, SEL_QKV,   BSE, E, SE,
        nullptr, SEL_SCORE, 0,   S, SS,
        E, 1.0f / 32.0f);

    // 5. softmax rows
    softmax_kernel<<<BATCH * S, 256>>>();

    // 6. attn_out = P @ Vt^T   (NT with Vt as [E,S] K-major)
    gemm_hmma<<<dim3(E / 128, S / 128, BATCH), NTHREADS, GEMM_SMEM_BYTES>>>(
        nullptr, SEL_SCORE, 0, S, SS,
        nullptr, SEL_VT,    0, S, SE,
        nullptr, SEL_AOUT,  0, E, SE,
        S, 1.0f);

    // 7. final = attn_out @ O^T
    gemm_hmma<<<dim3(E / 128, BS / 128, 1), NTHREADS, GEMM_SMEM_BYTES>>>(
        nullptr, SEL_AOUT, 0, E, 0,
        Ow,      SEL_EXT,  0, E, 0,
        out,     SEL_EXT,  0, E, 0,
        E, 1.0f);
}

// round 8
// speedup vs baseline: 2.5026x; 1.0254x over previous
#include <cuda_runtime.h>
#include <cstdint>

#define E 1024
#define R 16
#define BATCH 4
#define S 2048
#define BS (BATCH * S)

// ---------------- device scratch ----------------
__device__ float g_Weff[3][(size_t)E * E];                 // 12 MB
__device__ float g_QKV[3][(size_t)BATCH * S * E];          // 96 MB
__device__ float g_Vt[(size_t)BATCH * S * E];              // 32 MB (V^T per batch: [E][S])
__device__ float g_scores[(size_t)BATCH * S * S];          // 64 MB
__device__ float g_attnout[(size_t)BATCH * S * E];         // 32 MB

#define SEL_EXT   0
#define SEL_WEFF  1
#define SEL_QKV   2
#define SEL_SCORE 3
#define SEL_AOUT  4
#define SEL_VT    5

__device__ __forceinline__ float* resolve_buf(int sel, const float* ext) {
    switch (sel) {
        case SEL_WEFF:  return &g_Weff[0][0];
        case SEL_QKV:   return &g_QKV[0][0];
        case SEL_SCORE: return &g_scores[0];
        case SEL_AOUT:  return &g_attnout[0];
        case SEL_VT:    return &g_Vt[0];
        default:        return (float*)ext;
    }
}

// ---------------- bf16 helpers ----------------
__device__ __forceinline__ uint32_t bf16x2_rn(float x0, float x1) {
    uint32_t r;
    asm("cvt.rn.bf16x2.f32 %0, %1, %2;" : "=r"(r) : "f"(x1), "f"(x0));
    return r;
}
__device__ __forceinline__ float bf_lo_f(uint32_t w) { return __uint_as_float(w << 16); }
__device__ __forceinline__ float bf_hi_f(uint32_t w) { return __uint_as_float(w & 0xffff0000u); }

__device__ __forceinline__ void mma_bf16(float* c, const uint32_t* a, const uint32_t* b) {
    asm volatile("mma.sync.aligned.m16n8k16.row.col.f32.bf16.bf16.f32 "
        "{%0,%1,%2,%3}, {%4,%5,%6,%7}, {%8,%9}, {%0,%1,%2,%3};"
        : "+f"(c[0]), "+f"(c[1]), "+f"(c[2]), "+f"(c[3])
        : "r"(a[0]), "r"(a[1]), "r"(a[2]), "r"(a[3]), "r"(b[0]), "r"(b[1]));
}

// ---------------- W_eff = W + B @ A ----------------
__global__ __launch_bounds__(256) void weff_kernel(
    const float* __restrict__ Wq, const float* __restrict__ Wk, const float* __restrict__ Wv,
    const float* __restrict__ Aq, const float* __restrict__ Bq,
    const float* __restrict__ Ak, const float* __restrict__ Bk,
    const float* __restrict__ Av, const float* __restrict__ Bv)
{
    const int z = blockIdx.z;
    const float* W  = (z == 0) ? Wq : (z == 1) ? Wk : Wv;
    const float* Am = (z == 0) ? Aq : (z == 1) ? Ak : Av;
    const float* Bm = (z == 0) ? Bq : (z == 1) ? Bk : Bv;
    const int idx = blockIdx.x * 256 + threadIdx.x;
    const int f = idx >> 10;
    const int e = idx & 1023;
    float sum = W[idx];
#pragma unroll
    for (int r = 0; r < R; r++)
        sum += Bm[f * R + r] * Am[r * E + e];
    g_Weff[z][idx] = sum;
}

// ---------------- V transpose: Vt[b][e][s] = V[b][s][e] ----------------
__global__ __launch_bounds__(256) void transpose_v_kernel()
{
    __shared__ float t[32][33];
    const int b = blockIdx.z;
    const int s0 = blockIdx.x * 32;
    const int e0 = blockIdx.y * 32;
    const int tx = threadIdx.x & 31;
    const int ty = threadIdx.x >> 5;   // 0..7
    const float* V = &g_QKV[2][0] + (long long)b * S * E;
    float* Vt = &g_Vt[0] + (long long)b * S * E;
#pragma unroll
    for (int r = 0; r < 4; r++)
        t[ty + r * 8][tx] = V[(long long)(s0 + ty + r * 8) * E + e0 + tx];
    __syncthreads();
#pragma unroll
    for (int r = 0; r < 4; r++)
        Vt[(long long)(e0 + ty + r * 8) * S + s0 + tx] = t[tx][ty + r * 8];
}

// ---------------- split-BF16 3-term HMMA GEMM ----------------
// C[M,N] = alpha * A[M,K] @ B[N,K]^T (row-major). x -> bf16 hi + bf16 lo;
// acc += Ah*Bh + Al*Bh + Ah*Bl (Al*Bl dropped, ~2^-16 rel; fp32 TC accum).
// CTA 128x128x32, 8 warps (2x4), warp tile 64x32 of m16n8k16 fragments.
// TWO CTAs co-resident per SM (launch_bounds(256,2), regs<=128): latency is
// hidden by the sibling CTA, so the producer is a fused ldg->convert->sts
// pass with NO prefetch registers held across compute.
// Smem in MMA FRAGMENT ORDER; each 32-bit word = bf16x2 of (k, k+1).
//  A word: fb = (m>>4)*2 + kc; idx = fb*128 + ((m&7)*4 + tpair)*4 + ((m>>3)&1) + 2*khalf
//  B word: fb = (n>>3)*2 + kc; idx = fb*64  + ((n&7)*4 + tpair)*2 + khalf
// Word planes: aHi 0, aLo 2048, bHi 4096, bLo 6144; buffer stride 8192 words.
#define GEMM_SMEM_BYTES (2 * 8192 * 4)
#define NTHREADS 256

__global__ __launch_bounds__(NTHREADS, 2) void gemm_hmma(
    const float* extA, int selA, long long offA, int ldA, long long sA,
    const float* extB, int selB, long long offB, int ldB, long long sB,
    float* extC, int selC, long long offC, int ldC, long long sC,
    int K, float alpha)
{
    extern __shared__ uint32_t smw[];
    const int tid = threadIdx.x;
    const int wid = tid >> 5, lane = tid & 31;
    const int g = lane >> 2, t4 = lane & 3;
    const int warp_m = wid & 1, warp_n = wid >> 1;   // 2x4 warps, 64x32 warp tile

    const float* Ag = resolve_buf(selA, extA) + offA + (long long)blockIdx.z * sA
                      + (long long)blockIdx.y * 128 * ldA;
    const float* Bg = resolve_buf(selB, extB) + offB + (long long)blockIdx.z * sB
                      + (long long)blockIdx.x * 128 * ldB;
    float* Cg = resolve_buf(selC, extC) + offC + (long long)blockIdx.z * sC;

    float acc[4][4][4];
#pragma unroll
    for (int i = 0; i < 4; i++)
#pragma unroll
        for (int j = 0; j < 4; j++)
#pragma unroll
            for (int q = 0; q < 4; q++) acc[i][j][q] = 0.f;

    // fused producer: LDG one float4 of A and B, split+pack, STS to buffer s.
    // No registers held across the compute phase.
    auto ldg_sts = [&](int step, int s) {
        uint32_t* base = smw + s * 8192;
#pragma unroll
        for (int j = 0; j < 4; j++) {
            const int i = tid + j * NTHREADS;      // 0..1023 float4 slots
            const int m = i >> 3, q = i & 7;
            const int kc = q >> 2;                 // k16 chunk within step
            const int khalf = (q >> 1) & 1;        // k8 half within chunk
            const int tp = (q & 1) * 2;            // fragment k-pair base
            const float4 a4 = *reinterpret_cast<const float4*>(
                Ag + (long long)m * ldA + step * 32 + q * 4);
            const float4 b4 = *reinterpret_cast<const float4*>(
                Bg + (long long)m * ldB + step * 32 + q * 4);
            // A
            {
                const int fb = (m >> 4) * 2 + kc;
                const int reg = ((m >> 3) & 1) + 2 * khalf;
                const float xs[4] = { a4.x, a4.y, a4.z, a4.w };
#pragma unroll
                for (int w = 0; w < 2; w++) {
                    const float x0 = xs[w * 2], x1 = xs[w * 2 + 1];
                    const uint32_t h = bf16x2_rn(x0, x1);
                    const uint32_t l = bf16x2_rn(x0 - bf_lo_f(h), x1 - bf_hi_f(h));
                    const int idx = fb * 128 + ((m & 7) * 4 + tp + w) * 4 + reg;
                    base[idx] = h;
                    base[2048 + idx] = l;
                }
            }
            // B (row n = m)
            {
                const int fb = (m >> 3) * 2 + kc;
                const float ys[4] = { b4.x, b4.y, b4.z, b4.w };
#pragma unroll
                for (int w = 0; w < 2; w++) {
                    const float x0 = ys[w * 2], x1 = ys[w * 2 + 1];
                    const uint32_t h = bf16x2_rn(x0, x1);
                    const uint32_t l = bf16x2_rn(x0 - bf_lo_f(h), x1 - bf_hi_f(h));
                    const int idx = fb * 64 + ((m & 7) * 4 + tp + w) * 2 + khalf;
                    base[4096 + idx] = h;
                    base[6144 + idx] = l;
                }
            }
        }
    };

    auto compute = [&](int s) {
        const uint32_t* base = smw + s * 8192;
#pragma unroll
        for (int kc = 0; kc < 2; kc++) {
            uint32_t aF[2][4][4], bF[2][4][2];
#pragma unroll
            for (int mt = 0; mt < 4; mt++) {
                const int fb = (warp_m * 4 + mt) * 2 + kc;
                const uint4 h = *reinterpret_cast<const uint4*>(base + fb * 128 + lane * 4);
                const uint4 l = *reinterpret_cast<const uint4*>(base + 2048 + fb * 128 + lane * 4);
                aF[0][mt][0] = h.x; aF[0][mt][1] = h.y; aF[0][mt][2] = h.z; aF[0][mt][3] = h.w;
                aF[1][mt][0] = l.x; aF[1][mt][1] = l.y; aF[1][mt][2] = l.z; aF[1][mt][3] = l.w;
            }
#pragma unroll
            for (int nt = 0; nt < 4; nt++) {
                const int fb = (warp_n * 4 + nt) * 2 + kc;
                const uint2 h = *reinterpret_cast<const uint2*>(base + 4096 + fb * 64 + lane * 2);
                const uint2 l = *reinterpret_cast<const uint2*>(base + 6144 + fb * 64 + lane * 2);
                bF[0][nt][0] = h.x; bF[0][nt][1] = h.y;
                bF[1][nt][0] = l.x; bF[1][nt][1] = l.y;
            }
            // term 1: Ah * Bh
#pragma unroll
            for (int mt = 0; mt < 4; mt++)
#pragma unroll
                for (int nt = 0; nt < 4; nt++)
                    mma_bf16(acc[mt][nt], aF[0][mt], bF[0][nt]);
            // term 2: Al * Bh
#pragma unroll
            for (int mt = 0; mt < 4; mt++)
#pragma unroll
                for (int nt = 0; nt < 4; nt++)
                    mma_bf16(acc[mt][nt], aF[1][mt], bF[0][nt]);
            // term 3: Ah * Bl   (Al*Bl dropped)
#pragma unroll
            for (int mt = 0; mt < 4; mt++)
#pragma unroll
                for (int nt = 0; nt < 4; nt++)
                    mma_bf16(acc[mt][nt], aF[0][mt], bF[1][nt]);
        }
    };

    const int nsteps = K / 32;
    ldg_sts(0, 0);
    __syncthreads();
    for (int step = 0; step < nsteps; step++) {
        const int s = step & 1;
        if (step + 1 < nsteps) ldg_sts(step + 1, 1 - s);   // fill other buffer
        compute(s);
        __syncthreads();
    }

    // epilogue: warp rows warp_m*64 .. +63, cols warp_n*32 .. +31
#pragma unroll
    for (int mt = 0; mt < 4; mt++) {
        const long long row = (long long)blockIdx.y * 128 + warp_m * 64 + mt * 16 + g;
        const long long col0 = (long long)blockIdx.x * 128 + warp_n * 32;
#pragma unroll
        for (int nt = 0; nt < 4; nt++) {
            const long long col = col0 + nt * 8 + t4 * 2;
            float2 v0 = make_float2(acc[mt][nt][0] * alpha, acc[mt][nt][1] * alpha);
            float2 v1 = make_float2(acc[mt][nt][2] * alpha, acc[mt][nt][3] * alpha);
            *reinterpret_cast<float2*>(Cg + row * ldC + col) = v0;
            *reinterpret_cast<float2*>(Cg + (row + 8) * ldC + col) = v1;
        }
    }
}

// ---------------- row softmax over S=2048 ----------------
__global__ __launch_bounds__(256) void softmax_kernel()
{
    const long long row = blockIdx.x;
    float* p = &g_scores[0] + row * (long long)S;
    const int t = threadIdx.x;

    float v[8];
    float m = -1e30f;
#pragma unroll
    for (int i = 0; i < 8; i++) {
        v[i] = p[t + i * 256];
        m = fmaxf(m, v[i]);
    }
    __shared__ float red[8];
#pragma unroll
    for (int o = 16; o; o >>= 1) m = fmaxf(m, __shfl_xor_sync(0xffffffffu, m, o));
    if ((t & 31) == 0) red[t >> 5] = m;
    __syncthreads();
    float mx = red[0];
#pragma unroll
    for (int w = 1; w < 8; w++) mx = fmaxf(mx, red[w]);

    float s = 0.f;
#pragma unroll
    for (int i = 0; i < 8; i++) {
        v[i] = __expf(v[i] - mx);
        s += v[i];
    }
#pragma unroll
    for (int o = 16; o; o >>= 1) s += __shfl_xor_sync(0xffffffffu, s, o);
    __syncthreads();
    if ((t & 31) == 0) red[t >> 5] = s;
    __syncthreads();
    float tot = 0.f;
#pragma unroll
    for (int w = 0; w < 8; w++) tot += red[w];
    const float inv = 1.0f / tot;
#pragma unroll
    for (int i = 0; i < 8; i++) p[t + i * 256] = v[i] * inv;
}

// ---------------- launch ----------------
extern "C" void kernel_launch(void* const* d_in, const int* in_sizes, int n_in,
                              void* d_out, int out_size)
{
    (void)in_sizes; (void)n_in; (void)out_size;
    const float* query = (const float*)d_in[0];
    const float* key   = (const float*)d_in[1];
    const float* value = (const float*)d_in[2];
    const float* Qw    = (const float*)d_in[3];
    const float* Kw    = (const float*)d_in[4];
    const float* Vw    = (const float*)d_in[5];
    const float* Qa    = (const float*)d_in[6];
    const float* Qb    = (const float*)d_in[7];
    const float* Ka    = (const float*)d_in[8];
    const float* Kb    = (const float*)d_in[9];
    const float* Va    = (const float*)d_in[10];
    const float* Vb    = (const float*)d_in[11];
    const float* Ow    = (const float*)d_in[12];
    float* out = (float*)d_out;

    static bool attr_done = false;
    if (!attr_done) {
        cudaFuncSetAttribute(gemm_hmma, cudaFuncAttributeMaxDynamicSharedMemorySize,
                             GEMM_SMEM_BYTES);
        attr_done = true;
    }

    const long long EE  = (long long)E * E;
    const long long BSE = (long long)BATCH * S * E;
    const long long SE  = (long long)S * E;
    const long long SS  = (long long)S * S;

    // 1. fold LoRA into weights
    weff_kernel<<<dim3(E * E / 256, 1, 3), 256>>>(Qw, Kw, Vw, Qa, Qb, Ka, Kb, Va, Vb);

    // 2. Q/K/V projections: [8192,1024] = X @ Weff^T
    const float* xs[3] = { query, key, value };
    for (int p = 0; p < 3; p++) {
        gemm_hmma<<<dim3(E / 128, BS / 128, 1), NTHREADS, GEMM_SMEM_BYTES>>>(
            xs[p],   SEL_EXT,  0,       E, 0,
            nullptr, SEL_WEFF, p * EE,  E, 0,
            nullptr, SEL_QKV,  p * BSE, E, 0,
            E, 1.0f);
    }

    // 3. transpose V -> Vt[b][e][s]
    transpose_v_kernel<<<dim3(S / 32, E / 32, BATCH), 256>>>();

    // 4. scores = Q @ K^T / 32
    gemm_hmma<<<dim3(S / 128, S / 128, BATCH), NTHREADS, GEMM_SMEM_BYTES>>>(
        nullptr, SEL_QKV,   0,   E, SE,
        nullptr, SEL_QKV,   BSE, E, SE,
        nullptr, SEL_SCORE, 0,   S, SS,
        E, 1.0f / 32.0f);

    // 5. softmax rows
    softmax_kernel<<<BATCH * S, 256>>>();

    // 6. attn_out = P @ Vt^T   (NT with Vt as [E,S] K-major)
    gemm_hmma<<<dim3(E / 128, S / 128, BATCH), NTHREADS, GEMM_SMEM_BYTES>>>(
        nullptr, SEL_SCORE, 0, S, SS,
        nullptr, SEL_VT,    0, S, SE,
        nullptr, SEL_AOUT,  0, E, SE,
        S, 1.0f);

    // 7. final = attn_out @ O^T
    gemm_hmma<<<dim3(E / 128, BS / 128, 1), NTHREADS, GEMM_SMEM_BYTES>>>(
        nullptr, SEL_AOUT, 0, E, 0,
        Ow,      SEL_EXT,  0, E, 0,
        out,     SEL_EXT,  0, E, 0,
        E, 1.0f);
}

// round 9
// speedup vs baseline: 2.5200x; 1.0070x over previous
#include <cuda_runtime.h>
#include <cstdint>

#define E 1024
#define R 16
#define BATCH 4
#define S 2048
#define BS (BATCH * S)

// ---------------- device scratch ----------------
__device__ float g_Weff[3][(size_t)E * E];                 // 12 MB
__device__ float g_QKV[3][(size_t)BATCH * S * E];          // 96 MB
__device__ float g_Vt[(size_t)BATCH * S * E];              // 32 MB (V^T per batch: [E][S])
__device__ float g_scores[(size_t)BATCH * S * S];          // 64 MB
__device__ float g_attnout[(size_t)BATCH * S * E];         // 32 MB

#define SEL_EXT   0
#define SEL_WEFF  1
#define SEL_QKV   2
#define SEL_SCORE 3
#define SEL_AOUT  4
#define SEL_VT    5

__device__ __forceinline__ float* resolve_buf(int sel, const float* ext) {
    switch (sel) {
        case SEL_WEFF:  return &g_Weff[0][0];
        case SEL_QKV:   return &g_QKV[0][0];
        case SEL_SCORE: return &g_scores[0];
        case SEL_AOUT:  return &g_attnout[0];
        case SEL_VT:    return &g_Vt[0];
        default:        return (float*)ext;
    }
}

// ---------------- bf16 helpers ----------------
__device__ __forceinline__ uint32_t bf16x2_rn(float x0, float x1) {
    uint32_t r;
    asm("cvt.rn.bf16x2.f32 %0, %1, %2;" : "=r"(r) : "f"(x1), "f"(x0));
    return r;
}
__device__ __forceinline__ float bf_lo_f(uint32_t w) { return __uint_as_float(w << 16); }
__device__ __forceinline__ float bf_hi_f(uint32_t w) { return __uint_as_float(w & 0xffff0000u); }

__device__ __forceinline__ void mma_bf16(float* c, const uint32_t* a, const uint32_t* b) {
    asm volatile("mma.sync.aligned.m16n8k16.row.col.f32.bf16.bf16.f32 "
        "{%0,%1,%2,%3}, {%4,%5,%6,%7}, {%8,%9}, {%0,%1,%2,%3};"
        : "+f"(c[0]), "+f"(c[1]), "+f"(c[2]), "+f"(c[3])
        : "r"(a[0]), "r"(a[1]), "r"(a[2]), "r"(a[3]), "r"(b[0]), "r"(b[1]));
}

// ---------------- W_eff = W + B @ A ----------------
__global__ __launch_bounds__(256) void weff_kernel(
    const float* __restrict__ Wq, const float* __restrict__ Wk, const float* __restrict__ Wv,
    const float* __restrict__ Aq, const float* __restrict__ Bq,
    const float* __restrict__ Ak, const float* __restrict__ Bk,
    const float* __restrict__ Av, const float* __restrict__ Bv)
{
    const int z = blockIdx.z;
    const float* W  = (z == 0) ? Wq : (z == 1) ? Wk : Wv;
    const float* Am = (z == 0) ? Aq : (z == 1) ? Ak : Av;
    const float* Bm = (z == 0) ? Bq : (z == 1) ? Bk : Bv;
    const int idx = blockIdx.x * 256 + threadIdx.x;
    const int f = idx >> 10;
    const int e = idx & 1023;
    float sum = W[idx];
#pragma unroll
    for (int r = 0; r < R; r++)
        sum += Bm[f * R + r] * Am[r * E + e];
    g_Weff[z][idx] = sum;
}

// ---------------- V transpose: Vt[b][e][s] = V[b][s][e] ----------------
__global__ __launch_bounds__(256) void transpose_v_kernel()
{
    __shared__ float t[32][33];
    const int b = blockIdx.z;
    const int s0 = blockIdx.x * 32;
    const int e0 = blockIdx.y * 32;
    const int tx = threadIdx.x & 31;
    const int ty = threadIdx.x >> 5;   // 0..7
    const float* V = &g_QKV[2][0] + (long long)b * S * E;
    float* Vt = &g_Vt[0] + (long long)b * S * E;
#pragma unroll
    for (int r = 0; r < 4; r++)
        t[ty + r * 8][tx] = V[(long long)(s0 + ty + r * 8) * E + e0 + tx];
    __syncthreads();
#pragma unroll
    for (int r = 0; r < 4; r++)
        Vt[(long long)(e0 + ty + r * 8) * S + s0 + tx] = t[tx][ty + r * 8];
}

// ---------------- split-BF16 3-term HMMA GEMM, software-pipelined ----------------
// C[M,N] = alpha * A[M,K] @ B[N,K]^T (row-major). x -> bf16 hi + bf16 lo;
// acc += Ah*Bh + Al*Bh + Ah*Bl (Al*Bl dropped, ~2^-16 rel; fp32 TC accum).
// CTA 128x128x32, 8 warps (2x4), warp tile 64x32, 2 CTAs/SM.
// Main loop interleaves the producer (LDG / cvt+STS for step+1) with the two
// kc compute blocks of the current step so tensor issue overlaps producer work:
//   ldg_half0; compute_kc0; sts_half0+ldg_half1; compute_kc1; sts_half1; sync
// Smem word layout identical to R7/R8 (proven correct).
#define GEMM_SMEM_BYTES (2 * 8192 * 4)
#define NTHREADS 256

__global__ __launch_bounds__(NTHREADS, 2) void gemm_hmma(
    const float* extA, int selA, long long offA, int ldA, long long sA,
    const float* extB, int selB, long long offB, int ldB, long long sB,
    float* extC, int selC, long long offC, int ldC, long long sC,
    int K, float alpha)
{
    extern __shared__ uint32_t smw[];
    const int tid = threadIdx.x;
    const int wid = tid >> 5, lane = tid & 31;
    const int g = lane >> 2, t4 = lane & 3;
    const int warp_m = wid & 1, warp_n = wid >> 1;   // 2x4 warps, 64x32 warp tile

    const float* Ag = resolve_buf(selA, extA) + offA + (long long)blockIdx.z * sA
                      + (long long)blockIdx.y * 128 * ldA;
    const float* Bg = resolve_buf(selB, extB) + offB + (long long)blockIdx.z * sB
                      + (long long)blockIdx.x * 128 * ldB;
    float* Cg = resolve_buf(selC, extC) + offC + (long long)blockIdx.z * sC;

    float acc[4][4][4];
#pragma unroll
    for (int i = 0; i < 4; i++)
#pragma unroll
        for (int j = 0; j < 4; j++)
#pragma unroll
            for (int q = 0; q < 4; q++) acc[i][j][q] = 0.f;

    float4 va[2], vb[2];   // only 2 j-slots live at a time (16 regs)

    // load 2 of the 4 j-iterations' float4s for A and B tiles of `step`
    auto ldg_half = [&](int step, int h) {
#pragma unroll
        for (int j = 0; j < 2; j++) {
            const int i = tid + (2 * h + j) * NTHREADS;   // 0..1023 float4 slots
            const int m = i >> 3, q = i & 7;
            va[j] = *reinterpret_cast<const float4*>(Ag + (long long)m * ldA + step * 32 + q * 4);
            vb[j] = *reinterpret_cast<const float4*>(Bg + (long long)m * ldB + step * 32 + q * 4);
        }
    };

    // convert + scatter-store those 2 j-iterations into buffer s
    auto sts_half = [&](int s, int h) {
        uint32_t* base = smw + s * 8192;
#pragma unroll
        for (int j = 0; j < 2; j++) {
            const int i = tid + (2 * h + j) * NTHREADS;
            const int m = i >> 3, q = i & 7;
            const int kc = q >> 2;
            const int khalf = (q >> 1) & 1;
            const int tp = (q & 1) * 2;
            const float xs[4] = { va[j].x, va[j].y, va[j].z, va[j].w };
            const float ys[4] = { vb[j].x, vb[j].y, vb[j].z, vb[j].w };
            // A
            {
                const int fb = (m >> 4) * 2 + kc;
                const int reg = ((m >> 3) & 1) + 2 * khalf;
#pragma unroll
                for (int w = 0; w < 2; w++) {
                    const float x0 = xs[w * 2], x1 = xs[w * 2 + 1];
                    const uint32_t hh = bf16x2_rn(x0, x1);
                    const uint32_t ll = bf16x2_rn(x0 - bf_lo_f(hh), x1 - bf_hi_f(hh));
                    const int idx = fb * 128 + ((m & 7) * 4 + tp + w) * 4 + reg;
                    base[idx] = hh;
                    base[2048 + idx] = ll;
                }
            }
            // B (row n = m)
            {
                const int fb = (m >> 3) * 2 + kc;
#pragma unroll
                for (int w = 0; w < 2; w++) {
                    const float x0 = ys[w * 2], x1 = ys[w * 2 + 1];
                    const uint32_t hh = bf16x2_rn(x0, x1);
                    const uint32_t ll = bf16x2_rn(x0 - bf_lo_f(hh), x1 - bf_hi_f(hh));
                    const int idx = fb * 64 + ((m & 7) * 4 + tp + w) * 2 + khalf;
                    base[4096 + idx] = hh;
                    base[6144 + idx] = ll;
                }
            }
        }
    };

    // one kc (k16) block of compute on buffer s; bF loaded in two nt-halves
    // to cap live registers (aF 32 + bF 8).
    auto compute_kc = [&](int s, int kc) {
        const uint32_t* base = smw + s * 8192;
        uint32_t aF[2][4][4];
#pragma unroll
        for (int mt = 0; mt < 4; mt++) {
            const int fb = (warp_m * 4 + mt) * 2 + kc;
            const uint4 h = *reinterpret_cast<const uint4*>(base + fb * 128 + lane * 4);
            const uint4 l = *reinterpret_cast<const uint4*>(base + 2048 + fb * 128 + lane * 4);
            aF[0][mt][0] = h.x; aF[0][mt][1] = h.y; aF[0][mt][2] = h.z; aF[0][mt][3] = h.w;
            aF[1][mt][0] = l.x; aF[1][mt][1] = l.y; aF[1][mt][2] = l.z; aF[1][mt][3] = l.w;
        }
#pragma unroll
        for (int nh = 0; nh < 2; nh++) {
            uint32_t bF[2][2][2];
#pragma unroll
            for (int nt = 0; nt < 2; nt++) {
                const int fb = (warp_n * 4 + nh * 2 + nt) * 2 + kc;
                const uint2 h = *reinterpret_cast<const uint2*>(base + 4096 + fb * 64 + lane * 2);
                const uint2 l = *reinterpret_cast<const uint2*>(base + 6144 + fb * 64 + lane * 2);
                bF[0][nt][0] = h.x; bF[0][nt][1] = h.y;
                bF[1][nt][0] = l.x; bF[1][nt][1] = l.y;
            }
            // term 1: Ah * Bh
#pragma unroll
            for (int mt = 0; mt < 4; mt++)
#pragma unroll
                for (int nt = 0; nt < 2; nt++)
                    mma_bf16(acc[mt][nh * 2 + nt], aF[0][mt], bF[0][nt]);
            // term 2: Al * Bh
#pragma unroll
            for (int mt = 0; mt < 4; mt++)
#pragma unroll
                for (int nt = 0; nt < 2; nt++)
                    mma_bf16(acc[mt][nh * 2 + nt], aF[1][mt], bF[0][nt]);
            // term 3: Ah * Bl   (Al*Bl dropped)
#pragma unroll
            for (int mt = 0; mt < 4; mt++)
#pragma unroll
                for (int nt = 0; nt < 2; nt++)
                    mma_bf16(acc[mt][nh * 2 + nt], aF[0][mt], bF[1][nt]);
        }
    };

    const int nsteps = K / 32;
    // initial fill of buffer 0
    ldg_half(0, 0); sts_half(0, 0);
    ldg_half(0, 1); sts_half(0, 1);
    __syncthreads();

    for (int step = 0; step < nsteps; step++) {
        const int s = step & 1;
        const bool more = (step + 1 < nsteps);
        if (more) ldg_half(step + 1, 0);
        compute_kc(s, 0);
        if (more) { sts_half(1 - s, 0); ldg_half(step + 1, 1); }
        compute_kc(s, 1);
        if (more) sts_half(1 - s, 1);
        __syncthreads();
    }

    // epilogue: warp rows warp_m*64 .. +63, cols warp_n*32 .. +31
#pragma unroll
    for (int mt = 0; mt < 4; mt++) {
        const long long row = (long long)blockIdx.y * 128 + warp_m * 64 + mt * 16 + g;
        const long long col0 = (long long)blockIdx.x * 128 + warp_n * 32;
#pragma unroll
        for (int nt = 0; nt < 4; nt++) {
            const long long col = col0 + nt * 8 + t4 * 2;
            float2 v0 = make_float2(acc[mt][nt][0] * alpha, acc[mt][nt][1] * alpha);
            float2 v1 = make_float2(acc[mt][nt][2] * alpha, acc[mt][nt][3] * alpha);
            *reinterpret_cast<float2*>(Cg + row * ldC + col) = v0;
            *reinterpret_cast<float2*>(Cg + (row + 8) * ldC + col) = v1;
        }
    }
}

// ---------------- row softmax over S=2048 ----------------
__global__ __launch_bounds__(256) void softmax_kernel()
{
    const long long row = blockIdx.x;
    float* p = &g_scores[0] + row * (long long)S;
    const int t = threadIdx.x;

    float v[8];
    float m = -1e30f;
#pragma unroll
    for (int i = 0; i < 8; i++) {
        v[i] = p[t + i * 256];
        m = fmaxf(m, v[i]);
    }
    __shared__ float red[8];
#pragma unroll
    for (int o = 16; o; o >>= 1) m = fmaxf(m, __shfl_xor_sync(0xffffffffu, m, o));
    if ((t & 31) == 0) red[t >> 5] = m;
    __syncthreads();
    float mx = red[0];
#pragma unroll
    for (int w = 1; w < 8; w++) mx = fmaxf(mx, red[w]);

    float s = 0.f;
#pragma unroll
    for (int i = 0; i < 8; i++) {
        v[i] = __expf(v[i] - mx);
        s += v[i];
    }
#pragma unroll
    for (int o = 16; o; o >>= 1) s += __shfl_xor_sync(0xffffffffu, s, o);
    __syncthreads();
    if ((t & 31) == 0) red[t >> 5] = s;
    __syncthreads();
    float tot = 0.f;
#pragma unroll
    for (int w = 0; w < 8; w++) tot += red[w];
    const float inv = 1.0f / tot;
#pragma unroll
    for (int i = 0; i < 8; i++) p[t + i * 256] = v[i] * inv;
}

// ---------------- launch ----------------
extern "C" void kernel_launch(void* const* d_in, const int* in_sizes, int n_in,
                              void* d_out, int out_size)
{
    (void)in_sizes; (void)n_in; (void)out_size;
    const float* query = (const float*)d_in[0];
    const float* key   = (const float*)d_in[1];
    const float* value = (const float*)d_in[2];
    const float* Qw    = (const float*)d_in[3];
    const float* Kw    = (const float*)d_in[4];
    const float* Vw    = (const float*)d_in[5];
    const float* Qa    = (const float*)d_in[6];
    const float* Qb    = (const float*)d_in[7];
    const float* Ka    = (const float*)d_in[8];
    const float* Kb    = (const float*)d_in[9];
    const float* Va    = (const float*)d_in[10];
    const float* Vb    = (const float*)d_in[11];
    const float* Ow    = (const float*)d_in[12];
    float* out = (float*)d_out;

    static bool attr_done = false;
    if (!attr_done) {
        cudaFuncSetAttribute(gemm_hmma, cudaFuncAttributeMaxDynamicSharedMemorySize,
                             GEMM_SMEM_BYTES);
        attr_done = true;
    }

    const long long EE  = (long long)E * E;
    const long long BSE = (long long)BATCH * S * E;
    const long long SE  = (long long)S * E;
    const long long SS  = (long long)S * S;

    // 1. fold LoRA into weights
    weff_kernel<<<dim3(E * E / 256, 1, 3), 256>>>(Qw, Kw, Vw, Qa, Qb, Ka, Kb, Va, Vb);

    // 2. Q/K/V projections: [8192,1024] = X @ Weff^T
    const float* xs[3] = { query, key, value };
    for (int p = 0; p < 3; p++) {
        gemm_hmma<<<dim3(E / 128, BS / 128, 1), NTHREADS, GEMM_SMEM_BYTES>>>(
            xs[p],   SEL_EXT,  0,       E, 0,
            nullptr, SEL_WEFF, p * EE,  E, 0,
            nullptr, SEL_QKV,  p * BSE, E, 0,
            E, 1.0f);
    }

    // 3. transpose V -> Vt[b][e][s]
    transpose_v_kernel<<<dim3(S / 32, E / 32, BATCH), 256>>>();

    // 4. scores = Q @ K^T / 32
    gemm_hmma<<<dim3(S / 128, S / 128, BATCH), NTHREADS, GEMM_SMEM_BYTES>>>(
        nullptr, SEL_QKV,   0,   E, SE,
        nullptr, SEL_QKV,   BSE, E, SE,
        nullptr, SEL_SCORE, 0,   S, SS,
        E, 1.0f / 32.0f);

    // 5. softmax rows
    softmax_kernel<<<BATCH * S, 256>>>();

    // 6. attn_out = P @ Vt^T   (NT with Vt as [E,S] K-major)
    gemm_hmma<<<dim3(E / 128, S / 128, BATCH), NTHREADS, GEMM_SMEM_BYTES>>>(
        nullptr, SEL_SCORE, 0, S, SS,
        nullptr, SEL_VT,    0, S, SE,
        nullptr, SEL_AOUT,  0, E, SE,
        S, 1.0f);

    // 7. final = attn_out @ O^T
    gemm_hmma<<<dim3(E / 128, BS / 128, 1), NTHREADS, GEMM_SMEM_BYTES>>>(
        nullptr, SEL_AOUT, 0, E, 0,
        Ow,      SEL_EXT,  0, E, 0,
        out,     SEL_EXT,  0, E, 0,
        E, 1.0f);
}